// round 4
// baseline (speedup 1.0000x reference)
#include <cuda_runtime.h>
#include <cuda_bf16.h>
#include <cstdint>

// Problem constants
#define BSZ   128
#define CDIM  2048
#define HW    196          // 14*14
#define NDESC 32
#define NANS  1845
#define CD4   (CDIM / 4)   // 512 float4 per attended row

// Scratch (no allocations allowed)
__device__ float g_att[BSZ * CDIM];      // attended [B, C]
__device__ int   g_cnt[NDESC];           // samples per descriptor
__device__ int   g_list[NDESC * BSZ];    // sample ids per descriptor

// ---------------------------------------------------------------------------
// cp.async helpers
// ---------------------------------------------------------------------------
__device__ __forceinline__ void cp_async16(uint32_t dst_smem, const void* src) {
    asm volatile("cp.async.cg.shared.global [%0], [%1], 16;"
                 :: "r"(dst_smem), "l"(src));
}
__device__ __forceinline__ void cp_commit() {
    asm volatile("cp.async.commit_group;");
}
template<int N>
__device__ __forceinline__ void cp_wait() {
    asm volatile("cp.async.wait_group %0;" :: "n"(N));
}

// ---------------------------------------------------------------------------
// Kernel A: attended[b,c] = (1/196) * sum_hw mask[b,hw] * feat[b,c,hw]
// grid (32, 128), block 256. Warp processes 4 channels/iter (8 LDG.128 in
// flight), 2 iters -> 8 channels; block covers 64 channels.
// Block (0,0) also builds the grouping tables.
// ---------------------------------------------------------------------------
__global__ void __launch_bounds__(256)
attend_kernel(const float* __restrict__ mask,
              const float* __restrict__ feat,
              const int* __restrict__ inst32) {
    __shared__ float4 smask[49];
    const int b   = blockIdx.y;
    const int tid = threadIdx.x;

    const float4* mrow = reinterpret_cast<const float4*>(mask + (size_t)b * HW);
    if (tid < 49) smask[tid] = mrow[tid];
    __syncthreads();

    const int warp = tid >> 5;
    const int lane = tid & 31;

    #pragma unroll
    for (int it = 0; it < 2; ++it) {
        const int c0 = blockIdx.x * 64 + it * 32 + warp * 4;   // 4-aligned
        const float4* fr[4];
        #pragma unroll
        for (int j = 0; j < 4; ++j)
            fr[j] = reinterpret_cast<const float4*>(
                        feat + ((size_t)b * CDIM + c0 + j) * HW);

        float4 fa[4], fb[4];
        #pragma unroll
        for (int j = 0; j < 4; ++j) fa[j] = fr[j][lane];
        if (lane < 17) {
            #pragma unroll
            for (int j = 0; j < 4; ++j) fb[j] = fr[j][lane + 32];
        }

        float s[4];
        float4 ma = smask[lane];
        #pragma unroll
        for (int j = 0; j < 4; ++j)
            s[j] = fa[j].x * ma.x + fa[j].y * ma.y + fa[j].z * ma.z + fa[j].w * ma.w;
        if (lane < 17) {
            float4 mb = smask[lane + 32];
            #pragma unroll
            for (int j = 0; j < 4; ++j)
                s[j] += fb[j].x * mb.x + fb[j].y * mb.y + fb[j].z * mb.z + fb[j].w * mb.w;
        }
        #pragma unroll
        for (int j = 0; j < 4; ++j)
            #pragma unroll
            for (int off = 16; off > 0; off >>= 1)
                s[j] += __shfl_xor_sync(0xffffffffu, s[j], off);

        if (lane == 0) {
            float4 o = make_float4(s[0], s[1], s[2], s[3]);
            o.x *= (1.0f / HW); o.y *= (1.0f / HW);
            o.z *= (1.0f / HW); o.w *= (1.0f / HW);
            reinterpret_cast<float4*>(g_att)[((size_t)b * CDIM + c0) >> 2] = o;
        }
    }

    // ---- grouping tables, computed once by block (0,0) ----
    if (blockIdx.x == 0 && blockIdx.y == 0) {
        __shared__ int sh_inst[BSZ];
        __shared__ int sh_flag;
        if (tid == 0) sh_flag = 0;
        __syncthreads();
        if (tid < 64) {
            // int64 little-endian => odd 32-bit words of first 64 entries are 0
            if (inst32[2 * tid + 1] != 0) atomicOr(&sh_flag, 1);
        }
        __syncthreads();
        const bool is64 = (sh_flag == 0);
        if (tid < BSZ) sh_inst[tid] = is64 ? inst32[2 * tid] : inst32[tid];
        __syncthreads();
        if (tid == 0) {
            int cnt[NDESC];
            #pragma unroll
            for (int dd = 0; dd < NDESC; ++dd) cnt[dd] = 0;
            for (int bb = 0; bb < BSZ; ++bb) {
                int dd = sh_inst[bb];
                g_list[dd * BSZ + cnt[dd]++] = bb;
            }
            #pragma unroll
            for (int dd = 0; dd < NDESC; ++dd) g_cnt[dd] = cnt[dd];
        }
    }
}

// ---------------------------------------------------------------------------
// Kernel B: grouped GEMM, cp.async double-buffered W stream.
// preds[s,a] = sum_c att[s,c] * W[d,a,c] + bias[d,a]
// grid (58, 32). block 256 = 8 warps. Warp tile: 4 answers x 4 samples.
// K split into 8 chunks of 256 floats. W chunk (32 ans x 256 ch = 32KB)
// double-buffered in smem via cp.async; attended tile (4 x 2048 = 32KB)
// staged once per sample chunk. 96KB dynamic smem, 2 blocks/SM.
// ---------------------------------------------------------------------------
#define TSAMP 4
#define KCH4  64                  // float4 per chunk per answer row
#define NKC   8                   // 2048 / 256

__global__ void __launch_bounds__(256, 2)
gemm_kernel(const float* __restrict__ Wm,
            const float* __restrict__ bias,
            float* __restrict__ out) {
    const int d     = blockIdx.y;
    const int count = g_cnt[d];
    if (count == 0) return;

    extern __shared__ float4 dynsmem[];
    float4* Ws  = dynsmem;             // [2][32][64] float4  (64KB)
    float4* Att = dynsmem + 4096;      // [4][512]   float4   (32KB)
    __shared__ int s_b[TSAMP];

    const int tid  = threadIdx.x;
    const int warp = tid >> 5;
    const int lane = tid & 31;
    const int aw   = blockIdx.x * 32 + warp * 4;

    const float4* __restrict__ W4    = reinterpret_cast<const float4*>(Wm);
    const float4* __restrict__ gatt4 = reinterpret_cast<const float4*>(g_att);

    // per-thread W source bases (float4 units) for the 8 sub-copies of a chunk
    unsigned wsrc[8];
    {
        const int c4 = tid & 63;
        #pragma unroll
        for (int bs = 0; bs < 8; ++bs) {
            int a = blockIdx.x * 32 + (tid >> 6) + 4 * bs;
            if (a >= NANS) a = NANS - 1;            // clamp; dup reads hit L2
            wsrc[bs] = (unsigned)((d * NANS + a) * CD4) + c4;
        }
    }

    const uint32_t ws_smem  = (uint32_t)__cvta_generic_to_shared(Ws);
    const uint32_t att_smem = (uint32_t)__cvta_generic_to_shared(Att);

    const int nchunks = (count + TSAMP - 1) / TSAMP;

    for (int sc = 0; sc < nchunks; ++sc) {
        if (tid < TSAMP) {
            int si = sc * TSAMP + tid;
            s_b[tid] = (si < count) ? g_list[d * BSZ + si] : -1;
        }
        __syncthreads();

        // stage attended tile (full K; padding rows clamped to a valid
        // sample — their accumulators are never stored) + W chunk 0 (group 0)
        {
            int b0 = s_b[0];                        // always valid
            #pragma unroll
            for (int bs = 0; bs < 8; ++bs) {
                int ts = bs >> 1;
                int cc = ((bs & 1) << 8) + tid;
                int bb = s_b[ts]; if (bb < 0) bb = b0;
                cp_async16(att_smem + (unsigned)(ts * CD4 + cc) * 16u,
                           gatt4 + ((size_t)bb * CD4 + cc));
            }
            #pragma unroll
            for (int bs = 0; bs < 8; ++bs)
                cp_async16(ws_smem + (unsigned)(tid + 256 * bs) * 16u,
                           W4 + wsrc[bs]);
            cp_commit();
        }

        float acc[4][TSAMP];
        #pragma unroll
        for (int ta = 0; ta < 4; ++ta)
            #pragma unroll
            for (int ts = 0; ts < TSAMP; ++ts) acc[ta][ts] = 0.0f;

        #pragma unroll
        for (int kc = 0; kc < NKC; ++kc) {
            if (kc + 1 < NKC) {
                uint32_t dstbuf = ws_smem + (((kc + 1) & 1) ? 32768u : 0u);
                #pragma unroll
                for (int bs = 0; bs < 8; ++bs)
                    cp_async16(dstbuf + (unsigned)(tid + 256 * bs) * 16u,
                               W4 + wsrc[bs] + (unsigned)((kc + 1) * KCH4));
                cp_commit();
                cp_wait<1>();      // current buffer (and att on kc==0) ready
            } else {
                cp_wait<0>();
            }
            __syncthreads();

            const float4* wb = Ws + ((kc & 1) ? 2048 : 0) + (warp * 4) * KCH4;
            const float4* ab = Att + kc * KCH4;
            #pragma unroll
            for (int it = 0; it < 2; ++it) {
                const int cc = it * 32 + lane;
                float4 w[4], a[4];
                #pragma unroll
                for (int ta = 0; ta < 4; ++ta) w[ta] = wb[ta * KCH4 + cc];
                #pragma unroll
                for (int ts = 0; ts < TSAMP; ++ts) a[ts] = ab[ts * CD4 + cc];
                #pragma unroll
                for (int ta = 0; ta < 4; ++ta)
                    #pragma unroll
                    for (int ts = 0; ts < TSAMP; ++ts) {
                        acc[ta][ts] += w[ta].x * a[ts].x;
                        acc[ta][ts] += w[ta].y * a[ts].y;
                        acc[ta][ts] += w[ta].z * a[ts].z;
                        acc[ta][ts] += w[ta].w * a[ts].w;
                    }
            }
            __syncthreads();   // buffer consumed before next prefetch overwrites
        }

        // butterfly reduce: every lane ends with full sums
        #pragma unroll
        for (int ta = 0; ta < 4; ++ta)
            #pragma unroll
            for (int ts = 0; ts < TSAMP; ++ts)
                #pragma unroll
                for (int off = 16; off > 0; off >>= 1)
                    acc[ta][ts] += __shfl_xor_sync(0xffffffffu, acc[ta][ts], off);

        // lane l (<16) stores pair (ta = l/4, ts = l%4)
        if (lane < 16) {
            int ta = lane >> 2;
            int ts = lane & 3;
            int a  = aw + ta;
            int bb = s_b[ts];
            if (a < NANS && bb >= 0)
                out[(size_t)bb * NANS + a] = acc[ta][ts] + bias[(size_t)d * NANS + a];
        }
        __syncthreads();   // protect s_b / Att before next chunk rewrites
    }
}

// ---------------------------------------------------------------------------
extern "C" void kernel_launch(void* const* d_in, const int* in_sizes, int n_in,
                              void* d_out, int out_size) {
    const float* mask = (const float*)d_in[0];   // [B,1,14,14]
    const float* feat = (const float*)d_in[1];   // [B,C,14,14]
    const int*   inst = (const int*)d_in[2];     // [B] int64 or int32
    const float* Wm   = (const float*)d_in[3];   // [32,1845,2048]
    const float* bias = (const float*)d_in[4];   // [32,1845]
    float* out = (float*)d_out;                  // [B,1845]

    static const size_t GEMM_SMEM = 6144 * sizeof(float4);   // 96 KB
    cudaFuncSetAttribute(gemm_kernel,
                         cudaFuncAttributeMaxDynamicSharedMemorySize,
                         (int)GEMM_SMEM);

    attend_kernel<<<dim3(32, 128), 256>>>(mask, feat, inst);
    gemm_kernel<<<dim3((NANS + 31) / 32, NDESC), 256, GEMM_SMEM>>>(Wm, bias, out);
}